// round 5
// baseline (speedup 1.0000x reference)
#include <cuda_runtime.h>
#include <cstdint>

#define E_DIM 512
#define W_DIM 16
#define FRAMES 16000
#define NBC 16
#define OUT_PER_BC 128008
#define GROUPS_PER_BC 1000
#define G_PER_CTA 8
#define CTAS_PER_BC (GROUPS_PER_BC / G_PER_CTA)   // 125
#define NCTA (NBC * CTAS_PER_BC)                  // 2000
#define TPB 128

// Prepacked weight fragments, [term][ws][lane], term = ks*4 + nh*2 + b
__device__ uint32_t gBhi[4096];
__device__ uint32_t gBlo[4096];

__device__ __forceinline__ uint32_t bf16hi2(float x0, float x1) {
    uint32_t h;
    asm("cvt.rn.bf16x2.f32 %0, %1, %2;" : "=r"(h) : "f"(x1), "f"(x0));
    return h;
}
__device__ __forceinline__ uint32_t bf16lo2(float x0, float x1, uint32_t h) {
    float h0 = __uint_as_float(h << 16);
    float h1 = __uint_as_float(h & 0xFFFF0000u);
    uint32_t l;
    asm("cvt.rn.bf16x2.f32 %0, %1, %2;" : "=r"(l) : "f"(x1 - h1), "f"(x0 - h0));
    return l;
}
__device__ __forceinline__ void hmma(float c[4],
                                     uint32_t a0, uint32_t a1, uint32_t a2, uint32_t a3,
                                     uint32_t b0, uint32_t b1) {
    asm volatile(
        "mma.sync.aligned.m16n8k16.row.col.f32.bf16.bf16.f32 "
        "{%0,%1,%2,%3}, {%4,%5,%6,%7}, {%8,%9}, {%0,%1,%2,%3};"
        : "+f"(c[0]), "+f"(c[1]), "+f"(c[2]), "+f"(c[3])
        : "r"(a0), "r"(a1), "r"(a2), "r"(a3), "r"(b0), "r"(b1));
}
__device__ __forceinline__ void ldsm4(uint32_t a[4], uint32_t addr) {
    asm volatile("ldmatrix.sync.aligned.m8n8.x4.shared.b16 {%0,%1,%2,%3}, [%4];"
                 : "=r"(a[0]), "=r"(a[1]), "=r"(a[2]), "=r"(a[3]) : "r"(addr));
}
__device__ __forceinline__ void sts64(uint32_t addr, uint32_t a, uint32_t b) {
    asm volatile("st.shared.v2.b32 [%0], {%1, %2};" :: "r"(addr), "r"(a), "r"(b) : "memory");
}
__device__ __forceinline__ uint32_t smem_u32(const void* p) {
    uint32_t a;
    asm("{ .reg .u64 t; cvta.to.shared.u64 t, %1; cvt.u32.u64 %0, t; }" : "=r"(a) : "l"(p));
    return a;
}

__global__ void pack_weights(const float* __restrict__ bw) {
    int idx = blockIdx.x * blockDim.x + threadIdx.x;
    if (idx >= 4096) return;
    int lane = idx & 31;
    int rest = idx >> 5;
    int ws = rest & 3;
    int term = rest >> 2;
    int b = term & 1;
    int nh = (term >> 1) & 1;
    int ks = term >> 2;
    int n = (lane >> 2) + nh * 8;
    int k = ws * 128 + ks * 16 + (lane & 3) * 2 + b * 8;
    float x0 = bw[n * E_DIM + k];
    float x1 = bw[n * E_DIM + k + 1];
    uint32_t hi = bf16hi2(x0, x1);
    gBhi[idx] = hi;
    gBlo[idx] = bf16lo2(x0, x1, hi);
}

__global__ __launch_bounds__(TPB, 3)
void decoder_hmma(const float* __restrict__ mw,
                  const float* __restrict__ bw,
                  float* __restrict__ out)
{
    // per-warp A tiles: 16 rows x 128 bf16 (256 B/row), hi then lo, 8 KB/warp
    __shared__ __align__(16) char sA[4 * 8192];
    __shared__ float part[2][4][16][16];   // double-buffered per-warp K-slice partials
    __shared__ float carry[8];

    const int tid = threadIdx.x;
    const int ws = tid >> 5;
    const int lane = tid & 31;
    const int r = lane >> 2;
    const int c0 = (lane & 3) * 2;

    const uint32_t hiB = smem_u32(sA) + ws * 8192;
    const uint32_t loB = hiB + 4096;

    // weight fragments resident in registers (coalesced LDG, L2-hot)
    uint32_t bh[8][2][2], bl[8][2][2];
    #pragma unroll
    for (int ks = 0; ks < 8; ++ks)
        #pragma unroll
        for (int nh = 0; nh < 2; ++nh)
            #pragma unroll
            for (int b = 0; b < 2; ++b) {
                int term = ks * 4 + nh * 2 + b;
                bh[ks][nh][b] = gBhi[(term * 4 + ws) * 32 + lane];
                bl[ks][nh][b] = gBlo[(term * 4 + ws) * 32 + lane];
            }

    const int bc = blockIdx.x / CTAS_PER_BC;
    const int gi0 = (blockIdx.x - bc * CTAS_PER_BC) * G_PER_CTA;
    float* const obc = out + (long long)bc * OUT_PER_BC;

    // ---- carry-in: est[F0-1][8+j] computed scalar in fp32 (or 0 at bc start)
    if (gi0 > 0) {
        int w = 8 + ws * 2 + (lane >> 4);            // each warp covers 2 w's
        int seg = (lane & 15) * 32;
        const float4* xr = (const float4*)(mw + ((long long)bc * FRAMES + (long long)gi0 * 16 - 1) * E_DIM + seg);
        const float4* wr = (const float4*)(bw + w * E_DIM + seg);
        float s = 0.f;
        #pragma unroll
        for (int i = 0; i < 8; ++i) {
            float4 a = __ldg(xr + i);
            float4 b = __ldg(wr + i);
            s += a.x * b.x + a.y * b.y + a.z * b.z + a.w * b.w;
        }
        #pragma unroll
        for (int off = 8; off; off >>= 1)
            s += __shfl_down_sync(0xffffffffu, s, off, 16);
        if ((lane & 15) == 0) carry[ws * 2 + (lane >> 4)] = s;
    } else if (tid < 8) {
        carry[tid] = 0.f;
    }
    __syncthreads();

    const int lrow = lane & 15;
    const int lcs = (lane >> 4) & 1;

    // prefetch group 0, batch 0
    const float* gsrc0 = mw + ((long long)bc * FRAMES + (long long)gi0 * 16) * E_DIM + ws * 128;
    float4 vp[8];
    #pragma unroll
    for (int i = 0; i < 8; ++i)
        vp[i] = __ldg((const float4*)(gsrc0 + (long long)i * E_DIM) + lane);

    for (int g = 0; g < G_PER_CTA; ++g) {
        const long long f0 = (long long)(gi0 + g) * 16;
        const float* gsrc = mw + ((long long)bc * FRAMES + f0) * E_DIM + ws * 128;

        // issue batch-1 loads immediately (fly during batch-0 cvt/STS)
        float4 v1[8];
        #pragma unroll
        for (int i = 0; i < 8; ++i)
            v1[i] = __ldg((const float4*)(gsrc + (long long)(8 + i) * E_DIM) + lane);

        // cvt + swizzled STS, batch 0 (rows 0..7) from prefetched regs
        #pragma unroll
        for (int i = 0; i < 8; ++i) {
            uint32_t h0 = bf16hi2(vp[i].x, vp[i].y), h1 = bf16hi2(vp[i].z, vp[i].w);
            uint32_t l0 = bf16lo2(vp[i].x, vp[i].y, h0), l1 = bf16lo2(vp[i].z, vp[i].w, h1);
            uint32_t byte = (uint32_t)i * 256
                          + (uint32_t)(((lane >> 1) ^ (i & 7)) * 16)
                          + (uint32_t)((lane & 1) * 8);
            sts64(hiB + byte, h0, h1);
            sts64(loB + byte, l0, l1);
        }
        // batch 1 (rows 8..15)
        #pragma unroll
        for (int i = 0; i < 8; ++i) {
            int row = 8 + i;
            uint32_t h0 = bf16hi2(v1[i].x, v1[i].y), h1 = bf16hi2(v1[i].z, v1[i].w);
            uint32_t l0 = bf16lo2(v1[i].x, v1[i].y, h0), l1 = bf16lo2(v1[i].z, v1[i].w, h1);
            uint32_t byte = (uint32_t)row * 256
                          + (uint32_t)(((lane >> 1) ^ (row & 7)) * 16)
                          + (uint32_t)((lane & 1) * 8);
            sts64(hiB + byte, h0, h1);
            sts64(loB + byte, l0, l1);
        }
        __syncwarp();

        // ldmatrix + 3-pass split-precision HMMA
        float c[2][4] = {{0.f, 0.f, 0.f, 0.f}, {0.f, 0.f, 0.f, 0.f}};
        #pragma unroll
        for (int ks = 0; ks < 8; ++ks) {
            int chunk = 2 * ks + lcs;
            uint32_t byte = (uint32_t)lrow * 256 + (uint32_t)((chunk ^ (lrow & 7)) * 16);
            uint32_t ah[4], al[4];
            ldsm4(ah, hiB + byte);
            ldsm4(al, loB + byte);
            #pragma unroll
            for (int nh = 0; nh < 2; ++nh) {
                hmma(c[nh], ah[0], ah[1], ah[2], ah[3], bh[ks][nh][0], bh[ks][nh][1]);
                hmma(c[nh], ah[0], ah[1], ah[2], ah[3], bl[ks][nh][0], bl[ks][nh][1]);
                hmma(c[nh], al[0], al[1], al[2], al[3], bh[ks][nh][0], bh[ks][nh][1]);
            }
        }

        // prefetch next group's batch 0 (hides DRAM latency behind barrier/epilogue)
        if (g + 1 < G_PER_CTA) {
            const float* gn = gsrc + 16LL * E_DIM;
            #pragma unroll
            for (int i = 0; i < 8; ++i)
                vp[i] = __ldg((const float4*)(gn + (long long)i * E_DIM) + lane);
        }

        // write partials (double-buffered)
        float (*pb)[16][16] = part[g & 1];
        #pragma unroll
        for (int nh = 0; nh < 2; ++nh) {
            *(float2*)&pb[ws][r][c0 + nh * 8]     = make_float2(c[nh][0], c[nh][1]);
            *(float2*)&pb[ws][r + 8][c0 + nh * 8] = make_float2(c[nh][2], c[nh][3]);
        }
        __syncthreads();   // the ONLY CTA barrier per group

        // epilogue: each thread sums its needed est entries straight from part
        float* ob = obc + f0 * 8;
        if (tid < 120) {
            int k = tid >> 3, j = tid & 7;
            float a = pb[0][k][8 + j] + pb[1][k][8 + j]
                    + pb[2][k][8 + j] + pb[3][k][8 + j];
            float b2 = pb[0][k + 1][j] + pb[1][k + 1][j]
                     + pb[2][k + 1][j] + pb[3][k + 1][j];
            ob[(k + 1) * 8 + j] = a + b2;
        } else {
            int j = tid - 120;
            float e0  = pb[0][0][j] + pb[1][0][j] + pb[2][0][j] + pb[3][0][j];
            float e15 = pb[0][15][8 + j] + pb[1][15][8 + j]
                      + pb[2][15][8 + j] + pb[3][15][8 + j];
            ob[j] = carry[j] + e0;      // leading subframe: plain store, no atomic
            carry[j] = e15;             // trailing -> next group's carry
        }
    }

    // per-bc final subframe (s = 16000) owned by the last CTA of the bc
    if (gi0 + G_PER_CTA == GROUPS_PER_BC && tid >= 120)
        obc[(long long)FRAMES * 8 + (tid - 120)] = carry[tid - 120];
}

extern "C" void kernel_launch(void* const* d_in, const int* in_sizes, int n_in,
                              void* d_out, int out_size) {
    const float* mw = (const float*)d_in[0];   // [8,2,16000,512] f32
    const float* bw = (const float*)d_in[1];   // [16,512] f32
    float* out = (float*)d_out;                // [8,2,128008] f32

    pack_weights<<<32, 128>>>(bw);
    decoder_hmma<<<NCTA, TPB>>>(mw, bw, out);
}